// round 5
// baseline (speedup 1.0000x reference)
#include <cuda_runtime.h>
#include <cuda_fp16.h>
#include <math.h>
#include <complex>
#include <cstring>

// ============================================================================
// Equivariant convolution (e3nn-style), F=32, l<=2, 11 TP paths.
// R5: fp16 w2 in SMEM (3 CTAs/SM), launch_bounds(256,3), red.v4 scatter into
//     padded scratch + remap kernel (scale + relayout + re-zero).
// ============================================================================

#define NPATH 11
#define NW3J  363
#define NZ    115

// host-side copies (for fill_params)
static constexpr int c_PI[NPATH] = {0,0,0,1,1,1,1,2,2,2,2};
static constexpr int c_PJ[NPATH] = {0,1,2,0,1,1,2,0,1,2,2};
static constexpr int c_PK[NPATH] = {0,1,2,1,0,2,1,2,1,0,2};
static constexpr int c_PO[NPATH] = {0,1,10,35,44,53,98,143,168,213,238};
static constexpr int c_ZB[NPATH] = {0,1,4,9,18,21,36,45,70,85,90};

struct TPParams {
    float W[NW3J];
    float pw[NPATH];
    short z_woff[120];
    signed char z_nb[120];
    signed char z_bs[120];
    signed char z_yb[120];
};

// scatter scratch: [node][u(32)][12]  (q=0..8 used, 16B-aligned v4 slots)
// zero-initialized at module load; remap kernel re-zeroes after each read.
__device__ float g_scr[10000 * 384];

// ---------------- SMEM layout (bytes) ----------------
#define BLK   256
#define NWARP 8
#define EPG   4
static constexpr int SM_W2H = 0;                  // 352*64 half = 45056
static constexpr int SM_W1  = 45056;              // 512 f = 2048
static constexpr int SM_B1  = SM_W1 + 2048;       // 64 f = 256
static constexpr int SM_B2  = SM_B1 + 256;        // 352 f = 1408
static constexpr int SM_W3  = SM_B2 + 1408;       // 364 f = 1456
static constexpr int SM_H   = SM_W3 + 1456;       // 8 warps * 4*64 f = 8192
static constexpr int SM_EY  = SM_H + 8192;        // 8 * 40 f = 1280
static constexpr int SM_Z   = SM_EY + 1280;       // 8 * 116 f = 3712
static constexpr int SM_SI  = SM_Z + 3712;        // 8 * 8 int = 256
static constexpr int SM_TOT = SM_SI + 256;        // 63664 B (~62.2 KB)

__device__ __forceinline__ void red4(float* p, float a, float b, float c, float d) {
    asm volatile("red.global.add.v4.f32 [%0], {%1,%2,%3,%4};"
                 :: "l"(p), "f"(a), "f"(b), "f"(c), "f"(d) : "memory");
}

__global__ void __launch_bounds__(BLK, 3)
econv_kernel(const float* __restrict__ nodes, const float* __restrict__ pos,
             const int*   __restrict__ src,   const int*   __restrict__ dst,
             const float* __restrict__ w1,    const float* __restrict__ b1,
             const float* __restrict__ w2,    const float* __restrict__ b2,
             int nE, TPParams P)
{
    // device-local path constants (compile-time foldable under full unroll)
    constexpr int dPI[NPATH] = {0,0,0,1,1,1,1,2,2,2,2};
    constexpr int dPK[NPATH] = {0,1,2,1,0,2,1,2,1,0,2};
    constexpr int dZB[NPATH] = {0,1,4,9,18,21,36,45,70,85,90};
    constexpr int dXB[3] = {0,1,4};   // x feature base per l
    constexpr int dKB[3] = {0,1,4};   // output acc base per k

    extern __shared__ char smb[];
    __half* s_w2h = (__half*)(smb + SM_W2H);
    float*  s_w1  = (float*)(smb + SM_W1);
    float*  s_b1  = (float*)(smb + SM_B1);
    float*  s_b2  = (float*)(smb + SM_B2);
    float*  s_w3  = (float*)(smb + SM_W3);
    const int tid = threadIdx.x;

    // ---- stage block-resident weights ----
    for (int idx = tid; idx < 64 * 352; idx += BLK) {
        int j = idx / 352, q = idx - j * 352;
        s_w2h[q * 64 + j] = __float2half(w2[idx]);   // transpose: [q][j], fp16
    }
    for (int idx = tid; idx < 512; idx += BLK) s_w1[idx] = w1[idx];
    if (tid < 64)                              s_b1[tid] = b1[tid];
    for (int idx = tid; idx < 352; idx += BLK) s_b2[idx] = b2[idx];
    for (int idx = tid; idx < NW3J; idx += BLK) s_w3[idx] = P.W[idx];
    __syncthreads();

    const int warp = tid >> 5, lane = tid & 31;
    float* s_h  = (float*)(smb + SM_H)  + warp * 256;
    float* s_ey = (float*)(smb + SM_EY) + warp * 40;
    float* s_z  = (float*)(smb + SM_Z)  + warp * 116;
    int*   s_si = (int*)(smb + SM_SI)   + warp * 8;

    const int gwarp  = blockIdx.x * NWARP + warp;
    const int nwarps = gridDim.x * NWARP;
    const int ngroups = (nE + EPG - 1) / EPG;

    for (int g = gwarp; g < ngroups; g += nwarps) {
        __syncwarp();
        const int e0 = g * EPG;
        const int sub = lane >> 3, li = lane & 7;   // 8 lanes cooperate per edge
        const int e = e0 + sub;

        float cutv = 0.f, pvx = 0.f, pvy = 0.f, pvz = 0.f, dist = 0.f;
        int sv = 0, dv = 0;
        if (e < nE) {
            sv = src[e]; dv = dst[e];
            float ax = pos[3 * sv], ay = pos[3 * sv + 1], az = pos[3 * sv + 2];
            float bx = pos[3 * dv], by = pos[3 * dv + 1], bz = pos[3 * dv + 2];
            pvx = ax - bx; pvy = ay - by; pvz = az - bz;
            dist = sqrtf(pvx * pvx + pvy * pvy + pvz * pvz);
            if (dist < 4.0f) {                       // poly cutoff, RCUT=4
                float uu = dist * 0.25f;
                float u2 = uu * uu, u4 = u2 * u2;
                cutv = 1.0f - 6.0f * u4 * uu + 5.0f * u4 * u2;
            }
        }

        // ---- bessel + hidden layer (each lane: 8 h outputs of its edge) ----
        {
            float t = dist * 0.2f;                   // d / BESSEL_END
            float invt = (t > 0.f) ? (1.0f / t) : 1.0f;
            float mask = (t > 0.f && t < 1.f) ? 1.0f : 0.0f;
            const float CB = 0.6324555320336759f;    // sqrt(2/5)
            const float PIF = 3.14159265358979323846f;
            float bes[8];
            #pragma unroll
            for (int n = 0; n < 8; n++)
                bes[n] = CB * __sinf((float)(n + 1) * PIF * t) * invt * mask;
            #pragma unroll
            for (int jj = 0; jj < 8; jj++) {
                int j = li * 8 + jj;
                float z = s_b1[j];
                #pragma unroll
                for (int n = 0; n < 8; n++) z += bes[n] * s_w1[n * 64 + j];
                float hh = z / (1.0f + __expf(-z));  // silu
                s_h[sub * 64 + j] = hh * cutv;       // fold cutoff into h
            }
            if (li == 0) {
                float inv_d = 1.0f / fmaxf(dist, 1e-12f);
                float ux = pvx * inv_d, uy = pvy * inv_d, uz = pvz * inv_d;
                const float S3 = 1.7320508075688772f, S15 = 3.872983346207417f;
                const float S5H = 1.118033988749895f, S15H = 1.9364916731037085f;
                float* ey = s_ey + sub * 10;
                ey[0] = 1.0f;
                ey[1] = S3 * uy; ey[2] = S3 * uz; ey[3] = S3 * ux;
                ey[4] = S15 * ux * uy; ey[5] = S15 * uy * uz;
                ey[6] = S5H * (3.0f * uz * uz - 1.0f);
                ey[7] = S15 * ux * uz; ey[8] = S15H * (ux * ux - uy * uy);
                ey[9] = cutv;
                s_si[sub * 2 + 0] = sv; s_si[sub * 2 + 1] = dv;
            }
        }
        __syncwarp();

        // ---- radial layer 2: r[p][e] = b2*cut + sum_j (h*cut)[e][j] * w2h[p*32+lane][j]
        float r[NPATH][EPG];
        {
            float cc0 = s_ey[9], cc1 = s_ey[19], cc2 = s_ey[29], cc3 = s_ey[39];
            #pragma unroll
            for (int p = 0; p < NPATH; p++) {
                float b = s_b2[p * 32 + lane];
                r[p][0] = b * cc0; r[p][1] = b * cc1; r[p][2] = b * cc2; r[p][3] = b * cc3;
            }
            const int lx = lane & 15;                // 16-chunk XOR: 2-phase LDS64
            const __half* wrow = s_w2h + lane * 64;
            #pragma unroll 4
            for (int jc = 0; jc < 16; jc++) {
                int jce = jc ^ lx;                   // conflict-free phase order
                float4 h0 = *(const float4*)&s_h[0 * 64 + 4 * jce];
                float4 h1 = *(const float4*)&s_h[1 * 64 + 4 * jce];
                float4 h2 = *(const float4*)&s_h[2 * 64 + 4 * jce];
                float4 h3 = *(const float4*)&s_h[3 * 64 + 4 * jce];
                #pragma unroll
                for (int p = 0; p < NPATH; p++) {
                    uint2 wv = *(const uint2*)(wrow + p * 2048 + 4 * jce);
                    float2 wa = __half22float2(*(const __half2*)&wv.x);
                    float2 wb = __half22float2(*(const __half2*)&wv.y);
                    r[p][0] += wa.x * h0.x + wa.y * h0.y + wb.x * h0.z + wb.y * h0.w;
                    r[p][1] += wa.x * h1.x + wa.y * h1.y + wb.x * h1.z + wb.y * h1.w;
                    r[p][2] += wa.x * h2.x + wa.y * h2.y + wb.x * h2.z + wb.y * h2.w;
                    r[p][3] += wa.x * h3.x + wa.y * h3.y + wb.x * h3.z + wb.y * h3.w;
                }
            }
        }

        // ---- tensor product + scatter, one edge at a time ----
        #pragma unroll
        for (int ee = 0; ee < EPG; ee++) {
            float cc = s_ey[ee * 10 + 9];
            bool active = (cc != 0.0f);              // warp-uniform
            if (active) {
                // cooperative Z: Z[p][a][c] = sum_b W3J[p][a][b][c] * y[b]
                #pragma unroll
                for (int zz = 0; zz < 4; zz++) {
                    int ze = lane + zz * 32;
                    if (ze < NZ) {
                        int woff = P.z_woff[ze];
                        int nb = P.z_nb[ze], bs = P.z_bs[ze], yb = P.z_yb[ze];
                        float a = 0.f;
                        for (int b = 0; b < nb; b++)
                            a += s_w3[woff + b * bs] * s_ey[ee * 10 + yb + b];
                        s_z[ze] = a;
                    }
                }
            }
            __syncwarp();
            if (active) {
                int sv2 = s_si[ee * 2 + 0], dv2 = s_si[ee * 2 + 1];
                const float* row = nodes + (size_t)sv2 * 288;
                float x[9];
                x[0] = row[lane];
                #pragma unroll
                for (int d2 = 0; d2 < 3; d2++) x[1 + d2] = row[32 + 3 * lane + d2];
                #pragma unroll
                for (int d2 = 0; d2 < 5; d2++) x[4 + d2] = row[128 + 5 * lane + d2];

                float acc[9];
                #pragma unroll
                for (int q = 0; q < 9; q++) acc[q] = 0.f;

                #pragma unroll
                for (int p = 0; p < NPATH; p++) {
                    const int di = 2 * dPI[p] + 1, dk = 2 * dPK[p] + 1;
                    const int zb = dZB[p], xb = dXB[dPI[p]], kb = dKB[dPK[p]];
                    float wpu = P.pw[p] * r[p][ee];
                    #pragma unroll
                    for (int c = 0; c < dk; c++) {
                        float tt = 0.f;
                        #pragma unroll
                        for (int a = 0; a < di; a++)
                            tt += s_z[zb + a * dk + c] * x[xb + a];
                        acc[kb + c] += wpu * tt;
                    }
                }

                // padded-scratch scatter: [node][lane][12], q=0..8 (scale in remap)
                float* sb = g_scr + (size_t)dv2 * 384 + lane * 12;
                red4(sb,     acc[0], acc[1], acc[2], acc[3]);
                red4(sb + 4, acc[4], acc[5], acc[6], acc[7]);
                atomicAdd(sb + 8, acc[8]);
            }
            __syncwarp();
        }
    }
}

// relayout scratch -> out (apply 1/sqrt(25)), and re-zero scratch for the
// next graph replay (scratch is zero-initialized at load for the first call).
__global__ void remap_kernel(float* __restrict__ out, int total)
{
    int i = blockIdx.x * 256 + threadIdx.x;
    if (i >= total) return;
    int node = i / 288, f = i - node * 288;
    int u, q;
    if (f < 32)       { u = f; q = 0; }
    else if (f < 128) { int t = f - 32;  u = t / 3; q = 1 + (t - 3 * u); }
    else              { int t = f - 128; u = t / 5; q = 4 + (t - 5 * u); }
    int si = node * 384 + u * 12 + q;
    out[i] = 0.2f * g_scr[si];
    g_scr[si] = 0.f;
}

// ============================================================================
// Host: exact W3J construction (mirrors reference's complex-basis math)
// ============================================================================
namespace w3jhost {
typedef std::complex<double> cd;

static double factd(int n) { double r = 1; for (int i = 2; i <= n; i++) r *= i; return r; }

static double su2_cg(int j1, int j2, int j3, int m1, int m2, int m3) {
    if (m1 + m2 != m3) return 0.0;
    double pref = sqrt((2 * j3 + 1) * factd(j1 + j2 - j3) * factd(j1 - j2 + j3) *
                       factd(-j1 + j2 + j3) / factd(j1 + j2 + j3 + 1));
    pref *= sqrt(factd(j3 + m3) * factd(j3 - m3) * factd(j1 - m1) * factd(j1 + m1) *
                 factd(j2 - m2) * factd(j2 + m2));
    double s = 0.0;
    for (int k = 0; k <= j1 + j2 - j3; k++) {
        int d0 = k, d1 = j1 + j2 - j3 - k, d2 = j1 - m1 - k, d3 = j2 + m2 - k;
        int d4 = j3 - j2 + m1 + k, d5 = j3 - j1 - m2 + k;
        if (d0 < 0 || d1 < 0 || d2 < 0 || d3 < 0 || d4 < 0 || d5 < 0) continue;
        s += ((k & 1) ? -1.0 : 1.0) /
             (factd(d0) * factd(d1) * factd(d2) * factd(d3) * factd(d4) * factd(d5));
    }
    return pref * s;
}

static void qmat(int l, cd* q) {   // (2l+1)^2, row-major
    int n = 2 * l + 1;
    for (int i = 0; i < n * n; i++) q[i] = cd(0, 0);
    double is2 = 1.0 / sqrt(2.0);
    for (int m = -l; m < 0; m++) {
        q[(l + m) * n + (l - m)] = cd(is2, 0);
        q[(l + m) * n + (l + m)] = cd(0, -is2);
    }
    q[l * n + l] = cd(1, 0);
    for (int m = 1; m <= l; m++) {
        double sgn = (m & 1) ? -1.0 : 1.0;
        q[(l + m) * n + (l + m)] = cd(sgn * is2, 0);
        q[(l + m) * n + (l - m)] = cd(0, sgn * is2);
    }
    cd f = (l == 0) ? cd(1, 0) : ((l == 1) ? cd(0, -1) : cd(-1, 0));  // (-i)^l
    for (int i = 0; i < n * n; i++) q[i] *= f;
}

static void compute_w3j(int l1, int l2, int l3, float* outv) {
    int n1 = 2 * l1 + 1, n2 = 2 * l2 + 1, n3 = 2 * l3 + 1;
    double C[5][5][5];
    for (int i = 0; i < 5; i++) for (int k = 0; k < 5; k++) for (int m = 0; m < 5; m++)
        C[i][k][m] = 0.0;
    for (int m1 = -l1; m1 <= l1; m1++)
        for (int m2 = -l2; m2 <= l2; m2++)
            for (int m3 = -l3; m3 <= l3; m3++)
                C[l1 + m1][l2 + m2][l3 + m3] = su2_cg(l1, l2, l3, m1, m2, m3);
    cd q1[25], q2[25], q3[25];
    qmat(l1, q1); qmat(l2, q2); qmat(l3, q3);
    cd W[125];
    for (int j = 0; j < n1; j++)
        for (int l = 0; l < n2; l++)
            for (int nn = 0; nn < n3; nn++) {
                cd s(0, 0);
                for (int i = 0; i < n1; i++)
                    for (int k = 0; k < n2; k++)
                        for (int m = 0; m < n3; m++)
                            s += q1[i * n1 + j] * q2[k * n2 + l] *
                                 std::conj(q3[m * n3 + nn]) * C[i][k][m];
                W[(j * n2 + l) * n3 + nn] = s;
            }
    int tot = n1 * n2 * n3;
    double nr = 0, ni = 0;
    for (int t = 0; t < tot; t++) { nr += W[t].real() * W[t].real(); ni += W[t].imag() * W[t].imag(); }
    bool useR = sqrt(nr) >= sqrt(ni);
    double norm = sqrt(useR ? nr : ni);
    for (int t = 0; t < tot; t++)
        outv[t] = (float)((useR ? W[t].real() : W[t].imag()) / norm);
}

static void fill_params(TPParams& P) {
    for (int p = 0; p < NPATH; p++)
        compute_w3j(c_PI[p], c_PJ[p], c_PK[p], &P.W[c_PO[p]]);
    int cnt[3] = {0, 0, 0};
    for (int p = 0; p < NPATH; p++) cnt[c_PK[p]]++;
    for (int p = 0; p < NPATH; p++)
        P.pw[p] = (float)sqrt((2.0 * c_PK[p] + 1.0) / (double)cnt[c_PK[p]]);
    for (int p = 0; p < NPATH; p++) {
        int di = 2 * c_PI[p] + 1, dj = 2 * c_PJ[p] + 1, dk = 2 * c_PK[p] + 1;
        int yb = (c_PJ[p] == 0) ? 0 : ((c_PJ[p] == 1) ? 1 : 4);
        for (int a = 0; a < di; a++)
            for (int c = 0; c < dk; c++) {
                int zi = c_ZB[p] + a * dk + c;
                P.z_woff[zi] = (short)(c_PO[p] + a * dj * dk + c);
                P.z_nb[zi] = (signed char)dj;
                P.z_bs[zi] = (signed char)dk;
                P.z_yb[zi] = (signed char)yb;
            }
    }
    for (int zi = NZ; zi < 120; zi++) {
        P.z_woff[zi] = 0; P.z_nb[zi] = 0; P.z_bs[zi] = 0; P.z_yb[zi] = 0;
    }
}
}  // namespace w3jhost

extern "C" void kernel_launch(void* const* d_in, const int* in_sizes, int n_in,
                              void* d_out, int out_size)
{
    const float* nodes = (const float*)d_in[0];
    const float* pos   = (const float*)d_in[1];
    const int*   src   = (const int*)d_in[2];
    const int*   dst   = (const int*)d_in[3];
    const float* w1    = (const float*)d_in[4];
    const float* b1    = (const float*)d_in[5];
    const float* w2    = (const float*)d_in[6];
    const float* b2    = (const float*)d_in[7];
    float* out = (float*)d_out;
    const int nE = in_sizes[2];

    TPParams P;
    w3jhost::fill_params(P);

    cudaFuncSetAttribute(econv_kernel, cudaFuncAttributeMaxDynamicSharedMemorySize,
                         SM_TOT);
    econv_kernel<<<444, BLK, SM_TOT>>>(nodes, pos, src, dst, w1, b1, w2, b2, nE, P);
    remap_kernel<<<(out_size + 255) / 256, 256>>>(out, out_size);
}

// round 6
// speedup vs baseline: 1.1886x; 1.1886x over previous
#include <cuda_runtime.h>
#include <cuda_fp16.h>
#include <math.h>
#include <complex>
#include <cstring>

// ============================================================================
// Equivariant convolution (e3nn-style), F=32, l<=2, 11 TP paths.
// R6: EPG=2 (register demand fits 3 CTAs/SM WITHOUT spills), fp16 w2 in SMEM
//     (per-edge LDS bytes identical to the proven R4 config), v4-red scatter
//     into padded scratch + remap kernel.
// ============================================================================

#define NPATH 11
#define NW3J  363
#define NZ    115

// host-side copies (for fill_params)
static constexpr int c_PI[NPATH] = {0,0,0,1,1,1,1,2,2,2,2};
static constexpr int c_PJ[NPATH] = {0,1,2,0,1,1,2,0,1,2,2};
static constexpr int c_PK[NPATH] = {0,1,2,1,0,2,1,2,1,0,2};
static constexpr int c_PO[NPATH] = {0,1,10,35,44,53,98,143,168,213,238};
static constexpr int c_ZB[NPATH] = {0,1,4,9,18,21,36,45,70,85,90};

struct TPParams {
    float W[NW3J];
    float pw[NPATH];
    short z_woff[120];
    signed char z_nb[120];
    signed char z_bs[120];
    signed char z_yb[120];
};

// scatter scratch: [node][u(32)][12]  (q=0..8 used, 16B-aligned v4 slots)
// zero-initialized at module load; remap kernel re-zeroes after each read.
__device__ float g_scr[10000 * 384];

// ---------------- SMEM layout (bytes) ----------------
#define BLK   256
#define NWARP 8
#define EPG   2
static constexpr int SM_W2H = 0;                  // 352*64 half = 45056
static constexpr int SM_W1  = 45056;              // 512 f = 2048
static constexpr int SM_B1  = SM_W1 + 2048;       // 64 f = 256
static constexpr int SM_B2  = SM_B1 + 256;        // 352 f = 1408
static constexpr int SM_W3  = SM_B2 + 1408;       // 364 f = 1456
static constexpr int SM_H   = SM_W3 + 1456;       // 8 warps * 2*64 f = 4096
static constexpr int SM_EY  = SM_H + 4096;        // 8 * 20 f = 640
static constexpr int SM_Z   = SM_EY + 640;        // 8 * 116 f = 3712
static constexpr int SM_SI  = SM_Z + 3712;        // 8 * 4 int = 128
static constexpr int SM_TOT = SM_SI + 128;        // 58800 B (~57.4 KB)

__device__ __forceinline__ void red4(float* p, float a, float b, float c, float d) {
    asm volatile("red.global.add.v4.f32 [%0], {%1,%2,%3,%4};"
                 :: "l"(p), "f"(a), "f"(b), "f"(c), "f"(d) : "memory");
}

__global__ void __launch_bounds__(BLK, 3)
econv_kernel(const float* __restrict__ nodes, const float* __restrict__ pos,
             const int*   __restrict__ src,   const int*   __restrict__ dst,
             const float* __restrict__ w1,    const float* __restrict__ b1,
             const float* __restrict__ w2,    const float* __restrict__ b2,
             int nE, TPParams P)
{
    // device-local path constants (compile-time foldable under full unroll)
    constexpr int dPI[NPATH] = {0,0,0,1,1,1,1,2,2,2,2};
    constexpr int dPK[NPATH] = {0,1,2,1,0,2,1,2,1,0,2};
    constexpr int dZB[NPATH] = {0,1,4,9,18,21,36,45,70,85,90};
    constexpr int dXB[3] = {0,1,4};   // x feature base per l
    constexpr int dKB[3] = {0,1,4};   // output acc base per k

    extern __shared__ char smb[];
    __half* s_w2h = (__half*)(smb + SM_W2H);
    float*  s_w1  = (float*)(smb + SM_W1);
    float*  s_b1  = (float*)(smb + SM_B1);
    float*  s_b2  = (float*)(smb + SM_B2);
    float*  s_w3  = (float*)(smb + SM_W3);
    const int tid = threadIdx.x;

    // ---- stage block-resident weights ----
    for (int idx = tid; idx < 64 * 352; idx += BLK) {
        int j = idx / 352, q = idx - j * 352;
        s_w2h[q * 64 + j] = __float2half(w2[idx]);   // transpose: [q][j], fp16
    }
    for (int idx = tid; idx < 512; idx += BLK) s_w1[idx] = w1[idx];
    if (tid < 64)                              s_b1[tid] = b1[tid];
    for (int idx = tid; idx < 352; idx += BLK) s_b2[idx] = b2[idx];
    for (int idx = tid; idx < NW3J; idx += BLK) s_w3[idx] = P.W[idx];
    __syncthreads();

    const int warp = tid >> 5, lane = tid & 31;
    float* s_h  = (float*)(smb + SM_H)  + warp * (EPG * 64);
    float* s_ey = (float*)(smb + SM_EY) + warp * (EPG * 10);
    float* s_z  = (float*)(smb + SM_Z)  + warp * 116;
    int*   s_si = (int*)(smb + SM_SI)   + warp * (EPG * 2);

    const int gwarp  = blockIdx.x * NWARP + warp;
    const int nwarps = gridDim.x * NWARP;
    const int ngroups = (nE + EPG - 1) / EPG;

    for (int g = gwarp; g < ngroups; g += nwarps) {
        __syncwarp();
        const int e0 = g * EPG;
        const int sub = lane >> 4, li = lane & 15;  // 16 lanes cooperate per edge
        const int e = e0 + sub;

        float cutv = 0.f, pvx = 0.f, pvy = 0.f, pvz = 0.f, dist = 0.f;
        int sv = 0, dv = 0;
        if (e < nE) {
            sv = src[e]; dv = dst[e];
            float ax = pos[3 * sv], ay = pos[3 * sv + 1], az = pos[3 * sv + 2];
            float bx = pos[3 * dv], by = pos[3 * dv + 1], bz = pos[3 * dv + 2];
            pvx = ax - bx; pvy = ay - by; pvz = az - bz;
            dist = sqrtf(pvx * pvx + pvy * pvy + pvz * pvz);
            if (dist < 4.0f) {                       // poly cutoff, RCUT=4
                float uu = dist * 0.25f;
                float u2 = uu * uu, u4 = u2 * u2;
                cutv = 1.0f - 6.0f * u4 * uu + 5.0f * u4 * u2;
            }
        }

        // ---- bessel + hidden layer (each lane: 4 h outputs of its edge) ----
        {
            float t = dist * 0.2f;                   // d / BESSEL_END
            float invt = (t > 0.f) ? (1.0f / t) : 1.0f;
            float mask = (t > 0.f && t < 1.f) ? 1.0f : 0.0f;
            const float CB = 0.6324555320336759f;    // sqrt(2/5)
            const float PIF = 3.14159265358979323846f;
            float bes[8];
            #pragma unroll
            for (int n = 0; n < 8; n++)
                bes[n] = CB * __sinf((float)(n + 1) * PIF * t) * invt * mask;
            #pragma unroll
            for (int jj = 0; jj < 4; jj++) {
                int j = li * 4 + jj;
                float z = s_b1[j];
                #pragma unroll
                for (int n = 0; n < 8; n++) z += bes[n] * s_w1[n * 64 + j];
                float hh = z / (1.0f + __expf(-z));  // silu
                s_h[sub * 64 + j] = hh * cutv;       // fold cutoff into h
            }
            if (li == 0) {
                float inv_d = 1.0f / fmaxf(dist, 1e-12f);
                float ux = pvx * inv_d, uy = pvy * inv_d, uz = pvz * inv_d;
                const float S3 = 1.7320508075688772f, S15 = 3.872983346207417f;
                const float S5H = 1.118033988749895f, S15H = 1.9364916731037085f;
                float* ey = s_ey + sub * 10;
                ey[0] = 1.0f;
                ey[1] = S3 * uy; ey[2] = S3 * uz; ey[3] = S3 * ux;
                ey[4] = S15 * ux * uy; ey[5] = S15 * uy * uz;
                ey[6] = S5H * (3.0f * uz * uz - 1.0f);
                ey[7] = S15 * ux * uz; ey[8] = S15H * (ux * ux - uy * uy);
                ey[9] = cutv;
                s_si[sub * 2 + 0] = sv; s_si[sub * 2 + 1] = dv;
            }
        }
        __syncwarp();

        // ---- radial layer 2: r[p][e] = b2*cut + sum_j (h*cut)[e][j] * w2h[p*32+lane][j]
        float r[NPATH][EPG];
        {
            float cc0 = s_ey[9], cc1 = s_ey[19];
            #pragma unroll
            for (int p = 0; p < NPATH; p++) {
                float b = s_b2[p * 32 + lane];
                r[p][0] = b * cc0; r[p][1] = b * cc1;
            }
            const int lx = lane & 15;                // 16-chunk XOR order
            const __half* wrow = s_w2h + lane * 64;
            #pragma unroll 4
            for (int jc = 0; jc < 16; jc++) {
                int jce = jc ^ lx;                   // conflict-free phase order
                float4 h0 = *(const float4*)&s_h[0 * 64 + 4 * jce];
                float4 h1 = *(const float4*)&s_h[1 * 64 + 4 * jce];
                #pragma unroll
                for (int p = 0; p < NPATH; p++) {
                    uint2 wv = *(const uint2*)(wrow + p * 2048 + 4 * jce);
                    float2 wa = __half22float2(*(const __half2*)&wv.x);
                    float2 wb = __half22float2(*(const __half2*)&wv.y);
                    r[p][0] += wa.x * h0.x + wa.y * h0.y + wb.x * h0.z + wb.y * h0.w;
                    r[p][1] += wa.x * h1.x + wa.y * h1.y + wb.x * h1.z + wb.y * h1.w;
                }
            }
        }

        // ---- tensor product + scatter, one edge at a time ----
        #pragma unroll
        for (int ee = 0; ee < EPG; ee++) {
            float cc = s_ey[ee * 10 + 9];
            bool active = (cc != 0.0f);              // warp-uniform
            if (active) {
                // cooperative Z: Z[p][a][c] = sum_b W3J[p][a][b][c] * y[b]
                #pragma unroll
                for (int zz = 0; zz < 4; zz++) {
                    int ze = lane + zz * 32;
                    if (ze < NZ) {
                        int woff = P.z_woff[ze];
                        int nb = P.z_nb[ze], bs = P.z_bs[ze], yb = P.z_yb[ze];
                        float a = 0.f;
                        for (int b = 0; b < nb; b++)
                            a += s_w3[woff + b * bs] * s_ey[ee * 10 + yb + b];
                        s_z[ze] = a;
                    }
                }
            }
            __syncwarp();
            if (active) {
                int sv2 = s_si[ee * 2 + 0], dv2 = s_si[ee * 2 + 1];
                const float* row = nodes + (size_t)sv2 * 288;
                float x[9];
                x[0] = row[lane];
                #pragma unroll
                for (int d2 = 0; d2 < 3; d2++) x[1 + d2] = row[32 + 3 * lane + d2];
                #pragma unroll
                for (int d2 = 0; d2 < 5; d2++) x[4 + d2] = row[128 + 5 * lane + d2];

                float acc[9];
                #pragma unroll
                for (int q = 0; q < 9; q++) acc[q] = 0.f;

                #pragma unroll
                for (int p = 0; p < NPATH; p++) {
                    const int di = 2 * dPI[p] + 1, dk = 2 * dPK[p] + 1;
                    const int zb = dZB[p], xb = dXB[dPI[p]], kb = dKB[dPK[p]];
                    float wpu = P.pw[p] * r[p][ee];
                    #pragma unroll
                    for (int c = 0; c < dk; c++) {
                        float tt = 0.f;
                        #pragma unroll
                        for (int a = 0; a < di; a++)
                            tt += s_z[zb + a * dk + c] * x[xb + a];
                        acc[kb + c] += wpu * tt;
                    }
                }

                // padded-scratch scatter: [node][lane][12], q=0..8 (scale in remap)
                float* sb = g_scr + (size_t)dv2 * 384 + lane * 12;
                red4(sb,     acc[0], acc[1], acc[2], acc[3]);
                red4(sb + 4, acc[4], acc[5], acc[6], acc[7]);
                atomicAdd(sb + 8, acc[8]);
            }
            __syncwarp();
        }
    }
}

// relayout scratch -> out (apply 1/sqrt(25)), and re-zero scratch for the
// next graph replay (scratch is zero-initialized at load for the first call).
__global__ void remap_kernel(float* __restrict__ out, int total)
{
    int i = blockIdx.x * 256 + threadIdx.x;
    if (i >= total) return;
    int node = i / 288, f = i - node * 288;
    int u, q;
    if (f < 32)       { u = f; q = 0; }
    else if (f < 128) { int t = f - 32;  u = t / 3; q = 1 + (t - 3 * u); }
    else              { int t = f - 128; u = t / 5; q = 4 + (t - 5 * u); }
    int si = node * 384 + u * 12 + q;
    out[i] = 0.2f * g_scr[si];
    g_scr[si] = 0.f;
}

// ============================================================================
// Host: exact W3J construction (mirrors reference's complex-basis math)
// ============================================================================
namespace w3jhost {
typedef std::complex<double> cd;

static double factd(int n) { double r = 1; for (int i = 2; i <= n; i++) r *= i; return r; }

static double su2_cg(int j1, int j2, int j3, int m1, int m2, int m3) {
    if (m1 + m2 != m3) return 0.0;
    double pref = sqrt((2 * j3 + 1) * factd(j1 + j2 - j3) * factd(j1 - j2 + j3) *
                       factd(-j1 + j2 + j3) / factd(j1 + j2 + j3 + 1));
    pref *= sqrt(factd(j3 + m3) * factd(j3 - m3) * factd(j1 - m1) * factd(j1 + m1) *
                 factd(j2 - m2) * factd(j2 + m2));
    double s = 0.0;
    for (int k = 0; k <= j1 + j2 - j3; k++) {
        int d0 = k, d1 = j1 + j2 - j3 - k, d2 = j1 - m1 - k, d3 = j2 + m2 - k;
        int d4 = j3 - j2 + m1 + k, d5 = j3 - j1 - m2 + k;
        if (d0 < 0 || d1 < 0 || d2 < 0 || d3 < 0 || d4 < 0 || d5 < 0) continue;
        s += ((k & 1) ? -1.0 : 1.0) /
             (factd(d0) * factd(d1) * factd(d2) * factd(d3) * factd(d4) * factd(d5));
    }
    return pref * s;
}

static void qmat(int l, cd* q) {   // (2l+1)^2, row-major
    int n = 2 * l + 1;
    for (int i = 0; i < n * n; i++) q[i] = cd(0, 0);
    double is2 = 1.0 / sqrt(2.0);
    for (int m = -l; m < 0; m++) {
        q[(l + m) * n + (l - m)] = cd(is2, 0);
        q[(l + m) * n + (l + m)] = cd(0, -is2);
    }
    q[l * n + l] = cd(1, 0);
    for (int m = 1; m <= l; m++) {
        double sgn = (m & 1) ? -1.0 : 1.0;
        q[(l + m) * n + (l + m)] = cd(sgn * is2, 0);
        q[(l + m) * n + (l - m)] = cd(0, sgn * is2);
    }
    cd f = (l == 0) ? cd(1, 0) : ((l == 1) ? cd(0, -1) : cd(-1, 0));  // (-i)^l
    for (int i = 0; i < n * n; i++) q[i] *= f;
}

static void compute_w3j(int l1, int l2, int l3, float* outv) {
    int n1 = 2 * l1 + 1, n2 = 2 * l2 + 1, n3 = 2 * l3 + 1;
    double C[5][5][5];
    for (int i = 0; i < 5; i++) for (int k = 0; k < 5; k++) for (int m = 0; m < 5; m++)
        C[i][k][m] = 0.0;
    for (int m1 = -l1; m1 <= l1; m1++)
        for (int m2 = -l2; m2 <= l2; m2++)
            for (int m3 = -l3; m3 <= l3; m3++)
                C[l1 + m1][l2 + m2][l3 + m3] = su2_cg(l1, l2, l3, m1, m2, m3);
    cd q1[25], q2[25], q3[25];
    qmat(l1, q1); qmat(l2, q2); qmat(l3, q3);
    cd W[125];
    for (int j = 0; j < n1; j++)
        for (int l = 0; l < n2; l++)
            for (int nn = 0; nn < n3; nn++) {
                cd s(0, 0);
                for (int i = 0; i < n1; i++)
                    for (int k = 0; k < n2; k++)
                        for (int m = 0; m < n3; m++)
                            s += q1[i * n1 + j] * q2[k * n2 + l] *
                                 std::conj(q3[m * n3 + nn]) * C[i][k][m];
                W[(j * n2 + l) * n3 + nn] = s;
            }
    int tot = n1 * n2 * n3;
    double nr = 0, ni = 0;
    for (int t = 0; t < tot; t++) { nr += W[t].real() * W[t].real(); ni += W[t].imag() * W[t].imag(); }
    bool useR = sqrt(nr) >= sqrt(ni);
    double norm = sqrt(useR ? nr : ni);
    for (int t = 0; t < tot; t++)
        outv[t] = (float)((useR ? W[t].real() : W[t].imag()) / norm);
}

static void fill_params(TPParams& P) {
    for (int p = 0; p < NPATH; p++)
        compute_w3j(c_PI[p], c_PJ[p], c_PK[p], &P.W[c_PO[p]]);
    int cnt[3] = {0, 0, 0};
    for (int p = 0; p < NPATH; p++) cnt[c_PK[p]]++;
    for (int p = 0; p < NPATH; p++)
        P.pw[p] = (float)sqrt((2.0 * c_PK[p] + 1.0) / (double)cnt[c_PK[p]]);
    for (int p = 0; p < NPATH; p++) {
        int di = 2 * c_PI[p] + 1, dj = 2 * c_PJ[p] + 1, dk = 2 * c_PK[p] + 1;
        int yb = (c_PJ[p] == 0) ? 0 : ((c_PJ[p] == 1) ? 1 : 4);
        for (int a = 0; a < di; a++)
            for (int c = 0; c < dk; c++) {
                int zi = c_ZB[p] + a * dk + c;
                P.z_woff[zi] = (short)(c_PO[p] + a * dj * dk + c);
                P.z_nb[zi] = (signed char)dj;
                P.z_bs[zi] = (signed char)dk;
                P.z_yb[zi] = (signed char)yb;
            }
    }
    for (int zi = NZ; zi < 120; zi++) {
        P.z_woff[zi] = 0; P.z_nb[zi] = 0; P.z_bs[zi] = 0; P.z_yb[zi] = 0;
    }
}
}  // namespace w3jhost

extern "C" void kernel_launch(void* const* d_in, const int* in_sizes, int n_in,
                              void* d_out, int out_size)
{
    const float* nodes = (const float*)d_in[0];
    const float* pos   = (const float*)d_in[1];
    const int*   src   = (const int*)d_in[2];
    const int*   dst   = (const int*)d_in[3];
    const float* w1    = (const float*)d_in[4];
    const float* b1    = (const float*)d_in[5];
    const float* w2    = (const float*)d_in[6];
    const float* b2    = (const float*)d_in[7];
    float* out = (float*)d_out;
    const int nE = in_sizes[2];

    TPParams P;
    w3jhost::fill_params(P);

    cudaFuncSetAttribute(econv_kernel, cudaFuncAttributeMaxDynamicSharedMemorySize,
                         SM_TOT);
    econv_kernel<<<444, BLK, SM_TOT>>>(nodes, pos, src, dst, w1, b1, w2, b2, nE, P);
    remap_kernel<<<(out_size + 255) / 256, 256>>>(out, out_size);
}